// round 1
// baseline (speedup 1.0000x reference)
#include <cuda_runtime.h>

// ---------------------------------------------------------------------------
// GCN: out = blockdiag(adj, 64x) @ (x @ W)
//   GEMM1: H[32768,256] = X[32768,256] @ W[256,256]
//   GEMM2: Out[b][512,256] = adj[512,512] @ H[b][512,256], b = 0..63
// All fp32 row-major. All dims divisible by the tile sizes below.
// ---------------------------------------------------------------------------

#define BM 128
#define BN 128
#define BK 16
#define TM 8
#define TN 8
#define NTHREADS 256   // (BM/TM)*(BN/TN)

// Scratch for intermediate H = X @ W  (32768 x 256 fp32 = 32 MB)
__device__ float g_h[32768 * 256];

__global__ __launch_bounds__(NTHREADS)
void sgemm_tiled(const float* __restrict__ A,
                 const float* __restrict__ B,
                 float* __restrict__ C,
                 int M, int N, int K,
                 long aBatchStride, long bBatchStride, long cBatchStride) {
    A += (long)blockIdx.z * aBatchStride;
    B += (long)blockIdx.z * bBatchStride;
    C += (long)blockIdx.z * cBatchStride;

    __shared__ float As[BK][BM];   // A tile, transposed (k-major rows)
    __shared__ float Bs[BK][BN];

    const int tid  = threadIdx.x;
    const int tcol = tid % (BN / TN);   // 0..15
    const int trow = tid / (BN / TN);   // 0..15

    // A-tile load mapping: BM x BK floats = 512 float4, 2 per thread
    const int aRow  = tid / (BK / 4);   // 0..63  (then +64)
    const int aCol4 = tid % (BK / 4);   // 0..3
    // B-tile load mapping: BK x BN floats = 512 float4, 2 per thread
    const int bRow  = tid / (BN / 4);   // 0..7   (then +8)
    const int bCol4 = tid % (BN / 4);   // 0..31

    const float* Aptr = A + (long)(blockIdx.y * BM) * K;
    const float* Bptr = B + blockIdx.x * BN;

    float acc[TM][TN];
#pragma unroll
    for (int i = 0; i < TM; i++)
#pragma unroll
        for (int j = 0; j < TN; j++) acc[i][j] = 0.0f;

    for (int k0 = 0; k0 < K; k0 += BK) {
        // Load A tile (transpose into As[k][m])
#pragma unroll
        for (int it = 0; it < 2; it++) {
            int r = aRow + it * 64;
            float4 v = *(const float4*)(Aptr + (long)r * K + k0 + aCol4 * 4);
            As[aCol4 * 4 + 0][r] = v.x;
            As[aCol4 * 4 + 1][r] = v.y;
            As[aCol4 * 4 + 2][r] = v.z;
            As[aCol4 * 4 + 3][r] = v.w;
        }
        // Load B tile (direct)
#pragma unroll
        for (int it = 0; it < 2; it++) {
            int r = bRow + it * 8;
            *(float4*)(&Bs[r][bCol4 * 4]) =
                *(const float4*)(Bptr + (long)(k0 + r) * N + bCol4 * 4);
        }
        __syncthreads();

#pragma unroll
        for (int k = 0; k < BK; k++) {
            float4 m0 = *(const float4*)(&As[k][trow * TM]);
            float4 m1 = *(const float4*)(&As[k][trow * TM + 4]);
            float4 n0 = *(const float4*)(&Bs[k][tcol * TN]);
            float4 n1 = *(const float4*)(&Bs[k][tcol * TN + 4]);
            float regM[TM] = {m0.x, m0.y, m0.z, m0.w, m1.x, m1.y, m1.z, m1.w};
            float regN[TN] = {n0.x, n0.y, n0.z, n0.w, n1.x, n1.y, n1.z, n1.w};
#pragma unroll
            for (int i = 0; i < TM; i++)
#pragma unroll
                for (int j = 0; j < TN; j++)
                    acc[i][j] += regM[i] * regN[j];
        }
        __syncthreads();
    }

    float* Cptr = C + (long)(blockIdx.y * BM + trow * TM) * N + blockIdx.x * BN + tcol * TN;
#pragma unroll
    for (int i = 0; i < TM; i++) {
        float4 v0 = {acc[i][0], acc[i][1], acc[i][2], acc[i][3]};
        float4 v1 = {acc[i][4], acc[i][5], acc[i][6], acc[i][7]};
        *(float4*)(Cptr + (long)i * N + 0) = v0;
        *(float4*)(Cptr + (long)i * N + 4) = v1;
    }
}

extern "C" void kernel_launch(void* const* d_in, const int* in_sizes, int n_in,
                              void* d_out, int out_size) {
    const float* x      = (const float*)d_in[0];   // [32768, 256]
    // d_in[1] = batch (int64) — layout is contiguous blocks, unused
    const float* weight = (const float*)d_in[2];   // [256, 256]
    const float* adj    = (const float*)d_in[3];   // [512, 512]
    float* out          = (float*)d_out;           // [32768, 256]

    const int N_NODES = 512;
    const int N_BATCH = 64;
    const int D_IN    = 256;
    const int D_OUT   = 256;
    const int M1      = N_NODES * N_BATCH;         // 32768

    float* h;
    cudaGetSymbolAddress((void**)&h, g_h);

    // GEMM1: H = X @ W   (M=32768, N=256, K=256)
    {
        dim3 grid(D_OUT / BN, M1 / BM, 1);
        sgemm_tiled<<<grid, NTHREADS>>>(x, weight, h,
                                        M1, D_OUT, D_IN,
                                        0L, 0L, 0L);
    }
    // GEMM2: Out[b] = adj @ H[b]   (M=512, N=256, K=512), batched over 64
    {
        dim3 grid(D_OUT / BN, N_NODES / BM, N_BATCH);
        sgemm_tiled<<<grid, NTHREADS>>>(adj, h, out,
                                        N_NODES, D_OUT, N_NODES,
                                        0L, (long)N_NODES * D_OUT, (long)N_NODES * D_OUT);
    }
}